// round 5
// baseline (speedup 1.0000x reference)
#include <cuda_runtime.h>

#define NEGV -1000000000.0f

// Output layout (float offsets), reference return order:
// fwd_ts, fwd_ms, log_alpha, edge_log_alpha, log_betas, elb, ent, edge_ent
constexpr size_t O_FWD_TS    = 0;
constexpr size_t O_FWD_MS    = 131072;
constexpr size_t O_LOG_ALPHA = 262144;
constexpr size_t O_EDGE_LA   = 262208;
constexpr size_t O_LOG_BETAS = 393280;
constexpr size_t O_ELB       = 401472;
constexpr size_t O_ENT       = 17178688;
constexpr size_t O_EDGE_ENT  = 17178752;

// Staging geometry: PS%32==1 and (8*RS)%32==16 -> STS bank = p + 16l + const,
// all 32 lanes distinct => conflict-free stores from the compute side.
constexpr int RS    = 18;          // row stride (16 cols + 2 pad)
constexpr int PS    = 16 * RS + 1; // 289
constexpr int STAGE = 16 * PS;     // 4624 floats per warp

__device__ __forceinline__ float max8(const float* c) {
    float a = fmaxf(fmaxf(c[0], c[1]), fmaxf(c[2], c[3]));
    float b = fmaxf(fmaxf(c[4], c[5]), fmaxf(c[6], c[7]));
    return fmaxf(a, b);
}

// 64-thread blocks (2 warps). 2 lanes per problem, 8 rows per lane.
//  blockIdx.y < 4 : backward. b=blockIdx.x; warp w covers j = y*32+w*16+p.
//  blockIdx.y == 4: forward+entropy. blockIdx.x<2; b = x*32 + w*16 + p.
__global__ void __launch_bounds__(64)
tok_kernel(const float* __restrict__ fwd_ts,
           const float* __restrict__ bwd_ts,
           const int*   __restrict__ lengths,
           float* __restrict__ out)
{
    __shared__ float sh[2048 + 2 * STAGE];   // 45184 B

    const int tid  = threadIdx.x;
    const int lane = tid & 31;
    const int w    = tid >> 5;
    const int l8   = (lane & 1) * 8;     // first row of this lane
    const int p    = lane >> 1;          // problem within warp (0..15)
    const int q4   = lane & 3;           // flush: float4 slot
    const int g8   = lane >> 2;          // flush: row sub-index

    if (blockIdx.y < 4) {
        // ======================= backward scans =======================
        const int b   = blockIdx.x;
        const int len = lengths[b];
        const int j0w = (int)blockIdx.y * 32 + w * 16;
        const int j   = j0w + p;
        const int i0  = 127 - j;

        // stage bwd_ts[b] transposed to [c][r]
        const float* g = bwd_ts + (size_t)b * 2048;
        for (int x = tid; x < 2048; x += 64)
            sh[(x & 127) * 16 + (x >> 7)] = g[x];
        __syncthreads();

        float* stageW = sh + 2048 + w * STAGE;
        float* stp    = stageW + p * PS + l8 * RS;
        float* elbW   = out + O_ELB + (size_t)(b * 128 + j0w) * 2048;

        const int cb0 = (112 - j0w) & ~15;   // aligned start of live region

        float wv[8] = {0.f, 0.f, 0.f, 0.f, 0.f, 0.f, 0.f, 0.f};
        float lb = 0.f;

        for (int cb = 0; cb < 128; cb += 16) {
            if (cb < cb0) {
                // all-trivial prefix: bulk NEG fill, full 64B rows
                const float4 n4 = make_float4(NEGV, NEGV, NEGV, NEGV);
#pragma unroll 8
                for (int t = 0; t < 32; ++t) {
                    const int gg = t * 8 + g8;
                    *(float4*)&elbW[(size_t)gg * 128 + cb + q4 * 4] = n4;
                }
                continue;
            }
#pragma unroll 8
            for (int cc = 0; cc < 16; ++cc) {
                const int c = cb + cc;
                const float4 ta = *(const float4*)&sh[c * 16 + l8];
                const float4 tb = *(const float4*)&sh[c * 16 + l8 + 4];
                const float tv[8] = {ta.x, ta.y, ta.z, ta.w, tb.x, tb.y, tb.z, tb.w};
                const int kmax = min(j, c - i0) - l8;     // e_k  <=>  k <= kmax
                const float inc = __shfl_up_sync(0xffffffffu, wv[7], 1); // off-chain

                if (c < len) {
                    float cv[8];
                    cv[0] = (kmax >= 0) ? tv[0] + wv[0] : (l8 == 0 ? wv[0] : NEGV);
#pragma unroll
                    for (int k = 1; k < 8; ++k)
                        cv[k] = (kmax >= k) ? tv[k] + wv[k] : NEGV;

                    const float mxl = max8(cv);
                    float ev[8];
#pragma unroll
                    for (int k = 0; k < 8; ++k) ev[k] = __expf(cv[k] - mxl);
                    const float sl = ((ev[0] + ev[1]) + (ev[2] + ev[3])) +
                                     ((ev[4] + ev[5]) + (ev[6] + ev[7]));

                    const float mxo = __shfl_xor_sync(0xffffffffu, mxl, 1);
                    const float so  = __shfl_xor_sync(0xffffffffu, sl,  1);
                    const float mx  = fmaxf(mxl, mxo);
                    const float s   = sl * __expf(mxl - mx) + so * __expf(mxo - mx);
                    const float la  = mx + __logf(s);
                    lb = (c == len - 1) ? la : lb;

                    stp[0 * RS + cc] = (kmax >= 0) ? cv[0] : NEGV;
#pragma unroll
                    for (int k = 1; k < 8; ++k) stp[k * RS + cc] = cv[k];

#pragma unroll
                    for (int k = 7; k >= 1; --k) wv[k] = wv[k - 1];
                    wv[0] = (l8 == 0) ? la : inc;
                } else {
                    // tail: masks 0 -> cand = t + NEG where emask, else NEG
#pragma unroll
                    for (int k = 0; k < 8; ++k)
                        stp[k * RS + cc] = (kmax >= k) ? tv[k] + NEGV : NEGV;
                }
            }
            __syncwarp();
            // coalesced flush: rows of 16 floats (64B), 8 rows per pass
#pragma unroll 8
            for (int t = 0; t < 32; ++t) {
                const int gg = t * 8 + g8;
                const int pp = gg >> 4, rr = gg & 15;
                const float* s2 = stageW + pp * PS + rr * RS + q4 * 4;
                const float4 v = make_float4(s2[0], s2[1], s2[2], s2[3]);
                *(float4*)&elbW[(size_t)gg * 128 + cb + q4 * 4] = v;
            }
            __syncwarp();
        }
        if (l8 == 0)
            out[O_LOG_BETAS + (size_t)b * 128 + j] = lb;

    } else {
        // ================== forward + entropy scans ==================
        if (blockIdx.x >= 2) return;
        const int b   = (int)blockIdx.x * 32 + w * 16 + p;
        const int len = lengths[b];

        const float* tr = fwd_ts + (size_t)b * 2048 + (size_t)l8 * 128;
        float* ela  = out + O_EDGE_LA  + (size_t)b * 2048 + (size_t)l8 * 128;
        float* eent = out + O_EDGE_ENT + (size_t)b * 2048 + (size_t)l8 * 128;

        float wv[8] = {0.f, 0.f, 0.f, 0.f, 0.f, 0.f, 0.f, 0.f};
        float hv[8] = {0.f, 0.f, 0.f, 0.f, 0.f, 0.f, 0.f, 0.f};
        float laf = 0.f, hf = 0.f;
        float tv[8];
#pragma unroll
        for (int k = 0; k < 8; ++k) tv[k] = tr[k * 128];

#pragma unroll 8
        for (int jj = 0; jj < 128; ++jj) {
            float tn[8];
#pragma unroll
            for (int k = 0; k < 8; ++k)
                tn[k] = (jj < 127) ? tr[k * 128 + jj + 1] : 0.f;   // prefetch

            const float incw = __shfl_up_sync(0xffffffffu, wv[7], 1);
            const float inch = __shfl_up_sync(0xffffffffu, hv[7], 1);
            const int kmax = (jj < len) ? (jj - l8) : -1;

            float cv[8];
#pragma unroll
            for (int k = 0; k < 8; ++k)
                cv[k] = tv[k] + ((kmax >= k) ? wv[k] : NEGV);

            const float mxl = max8(cv);
            float ev[8];
#pragma unroll
            for (int k = 0; k < 8; ++k) ev[k] = __expf(cv[k] - mxl);
            const float sl = ((ev[0] + ev[1]) + (ev[2] + ev[3])) +
                             ((ev[4] + ev[5]) + (ev[6] + ev[7]));
            float ul = 0.f;
#pragma unroll
            for (int k = 0; k < 8; ++k) ul += ev[k] * (hv[k] - cv[k]);

            const float mxo = __shfl_xor_sync(0xffffffffu, mxl, 1);
            const float so  = __shfl_xor_sync(0xffffffffu, sl,  1);
            const float uo  = __shfl_xor_sync(0xffffffffu, ul,  1);
            const float mx  = fmaxf(mxl, mxo);
            const float f0  = __expf(mxl - mx);
            const float f1  = __expf(mxo - mx);
            const float s   = sl * f0 + so * f1;
            const float u   = ul * f0 + uo * f1;
            const float la  = mx + __logf(s);
            const float inv = __frcp_rn(s);
            const float hh  = la + u * inv;      // = sum q*(h + la - c)
            const float qf  = f0 * inv;

#pragma unroll
            for (int k = 0; k < 8; ++k) {
                ela[k * 128 + jj]  = cv[k];
                const float contrib = (kmax >= k)
                    ? (ev[k] * qf) * ((hv[k] + la) - cv[k]) : 0.f;
                eent[k * 128 + jj] = contrib;
            }

            laf = (jj == len - 1) ? la : laf;
            hf  = (jj == len - 1) ? hh : hf;

#pragma unroll
            for (int k = 7; k >= 1; --k) { wv[k] = wv[k - 1]; hv[k] = hv[k - 1]; }
            wv[0] = (l8 == 0) ? la : incw;
            hv[0] = (l8 == 0) ? hh : inch;
#pragma unroll
            for (int k = 0; k < 8; ++k) tv[k] = tn[k];
        }
        if (l8 == 0) {
            out[O_LOG_ALPHA + b] = laf;
            out[O_ENT + b]       = hf;
        }
    }
}

extern "C" void kernel_launch(void* const* d_in, const int* in_sizes, int n_in,
                              void* d_out, int out_size)
{
    const float* fwd_ts  = (const float*)d_in[0];
    const float* fwd_ms  = (const float*)d_in[1];
    const float* bwd_ts  = (const float*)d_in[2];
    const int*   lengths = (const int*)d_in[4];
    float* out = (float*)d_out;

    cudaMemcpyAsync(out + O_FWD_TS, fwd_ts, sizeof(float) * 131072,
                    cudaMemcpyDeviceToDevice);
    cudaMemcpyAsync(out + O_FWD_MS, fwd_ms, sizeof(float) * 131072,
                    cudaMemcpyDeviceToDevice);

    dim3 grid(64, 5);
    tok_kernel<<<grid, 64>>>(fwd_ts, bwd_ts, lengths, out);
}

// round 8
// speedup vs baseline: 3.4587x; 3.4587x over previous
#include <cuda_runtime.h>

#define NEGV -1000000000.0f

// Output layout (float offsets), reference return order:
// fwd_ts, fwd_ms, log_alpha, edge_log_alpha, log_betas, elb, ent, edge_ent
constexpr size_t O_FWD_TS    = 0;
constexpr size_t O_FWD_MS    = 131072;
constexpr size_t O_LOG_ALPHA = 262144;
constexpr size_t O_EDGE_LA   = 262208;
constexpr size_t O_LOG_BETAS = 393280;
constexpr size_t O_ELB       = 401472;
constexpr size_t O_ENT       = 17178688;
constexpr size_t O_EDGE_ENT  = 17178752;

__device__ __forceinline__ float red_max4(float v) {
    v = fmaxf(v, __shfl_xor_sync(0xffffffffu, v, 1));
    v = fmaxf(v, __shfl_xor_sync(0xffffffffu, v, 2));
    return v;
}
__device__ __forceinline__ float red_sum4(float v) {
    v += __shfl_xor_sync(0xffffffffu, v, 1);
    v += __shfl_xor_sync(0xffffffffu, v, 2);
    return v;
}

// Staging strides (floats): PS%32==1, RS%8==2 -> compute-side STS conflict-free.
constexpr int RS    = 34;
constexpr int PS    = 16 * RS + 1;   // 545
constexpr int STAGE = 8 * PS;        // 4360 floats / warp

// 64-thread blocks (2 warps), 4 lanes/problem, 4 rows/lane.
//  blockIdx.y < 8 : backward (pipelined combine — proven in R6).
//  blockIdx.y == 8: forward+entropy (R4 version — proven in R4).
__global__ void __launch_bounds__(64)
tok_kernel(const float* __restrict__ fwd_ts,
           const float* __restrict__ bwd_ts,
           const int*   __restrict__ lengths,
           float* __restrict__ out)
{
    __shared__ float sh[2048 + 2 * STAGE];   // 43072 B

    const int tid  = threadIdx.x;
    const int lane = tid & 31;
    const int w    = tid >> 5;
    const int l    = lane & 3;      // lane within 4-lane group
    const int p    = lane >> 2;     // problem within warp (0..7)
    const int rk0  = l * 4;         // first row of this lane
    const int q    = lane & 7;      // flush: float4 slot
    const int rsub = lane >> 3;     // flush: row sub-index

    if (blockIdx.y < 8) {
        // ============ backward scans (verbatim from passing R6) ============
        const int b   = blockIdx.x;
        const int len = lengths[b];
        const int j0w = (int)blockIdx.y * 16 + w * 8;
        const int j   = j0w + p;
        const int i0  = 127 - j;

        const float* g = bwd_ts + (size_t)b * 2048;
        for (int x = tid; x < 2048; x += 64)
            sh[(x & 127) * 16 + (x >> 7)] = g[x];
        __syncthreads();

        float* stageW = sh + 2048 + w * STAGE;
        float* stp    = stageW + p * PS + rk0 * RS;
        float* elbW   = out + O_ELB + (size_t)(b * 128 + j0w) * 2048;
        const int cb0 = (120 - j0w) & ~31;

        float w0 = 0.f, w1 = 0.f, w2 = 0.f, w3 = 0.f, la = 0.f, lb = 0.f;
        float cv0, cv1, cv2, cv3, M, S, t0c;
        {   // initial precompute for column cb0 (w-state all zero)
            const float4 t4 = *(const float4*)&sh[cb0 * 16 + rk0];
            const int km = min(j, cb0 - i0) - rk0;
            cv0 = (l > 0 && km >= 0) ? t4.x : NEGV;
            cv1 = (km >= 1) ? t4.y : NEGV;
            cv2 = (km >= 2) ? t4.z : NEGV;
            cv3 = (km >= 3) ? t4.w : NEGV;
            float mxl = fmaxf(fmaxf(cv0, cv1), fmaxf(cv2, cv3));
            float sl = (__expf(cv0 - mxl) + __expf(cv1 - mxl)) +
                       (__expf(cv2 - mxl) + __expf(cv3 - mxl));
            float Mt = fmaxf(mxl, __shfl_xor_sync(0xffffffffu, mxl, 1));
            Mt = fmaxf(Mt, __shfl_xor_sync(0xffffffffu, Mt, 2));
            float sg = sl * __expf(mxl - Mt);
            sg += __shfl_xor_sync(0xffffffffu, sg, 1);
            sg += __shfl_xor_sync(0xffffffffu, sg, 2);
            M = Mt; S = sg; t0c = t4.x;
        }

        for (int cb = 0; cb < 128; cb += 32) {
            if (cb < cb0) {   // all-trivial prefix: bulk NEG fill
                const float4 n4 = make_float4(NEGV, NEGV, NEGV, NEGV);
#pragma unroll 8
                for (int t = 0; t < 32; ++t) {
                    const int gg = t * 4 + rsub;
                    *(float4*)&elbW[(size_t)gg * 128 + cb + q * 4] = n4;
                }
                continue;
            }
#pragma unroll 2
            for (int cc = 0; cc < 32; ++cc) {
                const int c = cb + cc;
                if (c < len) {   // uniform branch
                    // ---- precompute column c+1 (independent of la) ----
                    const int cn = min(c + 1, 127);
                    const float4 t4 = *(const float4*)&sh[cn * 16 + rk0];
                    const float upn = __shfl_up_sync(0xffffffffu, w3, 1);
                    const int kmn = min(j, c + 1 - i0) - rk0;
                    const float p0 = (l > 0 && kmn >= 0) ? t4.x + upn : NEGV;
                    const float p1 = (kmn >= 1) ? t4.y + w0 : NEGV;
                    const float p2 = (kmn >= 2) ? t4.z + w1 : NEGV;
                    const float p3 = (kmn >= 3) ? t4.w + w2 : NEGV;
                    float mxl = fmaxf(fmaxf(p0, p1), fmaxf(p2, p3));
                    float sl = (__expf(p0 - mxl) + __expf(p1 - mxl)) +
                               (__expf(p2 - mxl) + __expf(p3 - mxl));
                    float Mt = fmaxf(mxl, __shfl_xor_sync(0xffffffffu, mxl, 1));
                    Mt = fmaxf(Mt, __shfl_xor_sync(0xffffffffu, Mt, 2));
                    float sg = sl * __expf(mxl - Mt);
                    sg += __shfl_xor_sync(0xffffffffu, sg, 1);
                    sg += __shfl_xor_sync(0xffffffffu, sg, 2);
                    // ---- combine column c (short serial chain, lane0) ----
                    const bool  e0 = (c >= i0);
                    const float c0 = (e0 ? t0c : 0.f) + la;
                    const float mx = fmaxf(M, c0);
                    const float s  = S * __expf(M - mx) + __expf(c0 - mx);
                    const float lan = mx + __logf(s);
                    lb = (c == len - 1) ? lan : lb;
                    // ---- outputs column c ----
                    const int km = min(j, c - i0) - rk0;
                    stp[cc]          = (l == 0) ? (e0 ? c0 : NEGV)
                                                : ((km >= 0) ? cv0 : NEGV);
                    stp[RS + cc]     = (km >= 1) ? cv1 : NEGV;
                    stp[2 * RS + cc] = (km >= 2) ? cv2 : NEGV;
                    stp[3 * RS + cc] = (km >= 3) ? cv3 : NEGV;
                    // ---- rotate state ----
                    w3 = w2; w2 = w1; w1 = w0;
                    w0 = (l == 0) ? lan : upn;
                    la = lan;
                    cv0 = p0; cv1 = p1; cv2 = p2; cv3 = p3;
                    M = Mt; S = sg; t0c = t4.x;
                } else {
                    // tail: cand = t + NEG where emask, else NEG
                    const float4 t4 = *(const float4*)&sh[c * 16 + rk0];
                    const int km = min(j, c - i0) - rk0;
                    stp[cc]          = (km >= 0) ? t4.x + NEGV : NEGV;
                    stp[RS + cc]     = (km >= 1) ? t4.y + NEGV : NEGV;
                    stp[2 * RS + cc] = (km >= 2) ? t4.z + NEGV : NEGV;
                    stp[3 * RS + cc] = (km >= 3) ? t4.w + NEGV : NEGV;
                }
            }
            __syncwarp();
#pragma unroll 4
            for (int t = 0; t < 32; ++t) {
                const int gg = t * 4 + rsub;
                const int pp = gg >> 4, rr = gg & 15;
                const float* s2 = stageW + pp * PS + rr * RS + q * 4;
                const float4 v = make_float4(s2[0], s2[1], s2[2], s2[3]);
                *(float4*)&elbW[(size_t)gg * 128 + cb + q * 4] = v;
            }
            __syncwarp();
        }
        if (l == 0)
            out[O_LOG_BETAS + (size_t)b * 128 + j] = lb;

    } else {
        // ====== forward + entropy scans (verbatim from passing R4) ======
        if (blockIdx.x >= 8 || w != 0) return;
        const int b   = (int)blockIdx.x * 8 + p;
        const int len = lengths[b];

        const float* tr = fwd_ts + (size_t)b * 2048 + (size_t)rk0 * 128;
        float* stLA = sh;             // warp-private (only warp 0 alive)
        float* stH  = sh + STAGE;
        float* elaW  = out + O_EDGE_LA  + (size_t)blockIdx.x * 8 * 2048;
        float* eentW = out + O_EDGE_ENT + (size_t)blockIdx.x * 8 * 2048;

        float w0 = 0.f, w1 = 0.f, w2 = 0.f, w3 = 0.f;
        float h0 = 0.f, h1 = 0.f, h2 = 0.f, h3 = 0.f;
        float laf = 0.f, hf = 0.f;
        float t0 = tr[0], t1 = tr[128], t2 = tr[256], t3 = tr[384];
        float* st = stLA + p * PS + rk0 * RS;
        float* sh2 = stH + p * PS + rk0 * RS;

        for (int cb = 0; cb < 128; cb += 32) {
#pragma unroll 2
            for (int cc = 0; cc < 32; ++cc) {
                const int jj = cb + cc;
                float n0 = 0.f, n1 = 0.f, n2 = 0.f, n3 = 0.f;
                if (jj < 127) {   // prefetch next column (off-chain)
                    n0 = tr[jj + 1];       n1 = tr[128 + jj + 1];
                    n2 = tr[256 + jj + 1]; n3 = tr[384 + jj + 1];
                }
                const bool in = (jj < len);
                const bool m0 = in && (rk0     <= jj);
                const bool m1 = in && (rk0 + 1 <= jj);
                const bool m2 = in && (rk0 + 2 <= jj);
                const bool m3 = in && (rk0 + 3 <= jj);
                const float c0 = t0 + (m0 ? w0 : NEGV);
                const float c1 = t1 + (m1 ? w1 : NEGV);
                const float c2 = t2 + (m2 ? w2 : NEGV);
                const float c3 = t3 + (m3 ? w3 : NEGV);
                const float mx = red_max4(fmaxf(fmaxf(c0, c1), fmaxf(c2, c3)));
                const float e0 = __expf(c0 - mx), e1 = __expf(c1 - mx);
                const float e2 = __expf(c2 - mx), e3 = __expf(c3 - mx);
                const float ss = red_sum4((e0 + e1) + (e2 + e3));
                const float la = mx + __logf(ss);
                const float inv = __frcp_rn(ss);
                const float g0 = m0 ? (e0 * inv) * ((h0 + la) - c0) : 0.f;
                const float g1 = m1 ? (e1 * inv) * ((h1 + la) - c1) : 0.f;
                const float g2 = m2 ? (e2 * inv) * ((h2 + la) - c2) : 0.f;
                const float g3 = m3 ? (e3 * inv) * ((h3 + la) - c3) : 0.f;
                const float hh = red_sum4((g0 + g1) + (g2 + g3));

                laf = (jj == len - 1) ? la : laf;
                hf  = (jj == len - 1) ? hh : hf;

                st[cc] = c0;  st[RS + cc] = c1;  st[2 * RS + cc] = c2;  st[3 * RS + cc] = c3;
                sh2[cc] = g0; sh2[RS + cc] = g1; sh2[2 * RS + cc] = g2; sh2[3 * RS + cc] = g3;

                const float upw = __shfl_up_sync(0xffffffffu, w3, 1);
                const float uph = __shfl_up_sync(0xffffffffu, h3, 1);
                w3 = w2; w2 = w1; w1 = w0; w0 = (l == 0) ? la : upw;
                h3 = h2; h2 = h1; h1 = h0; h0 = (l == 0) ? hh : uph;
                t0 = n0; t1 = n1; t2 = n2; t3 = n3;
            }
            __syncwarp();
#pragma unroll 4
            for (int t = 0; t < 32; ++t) {
                const int gg = t * 4 + rsub;
                const int pp = gg >> 4, rr = gg & 15;
                const float* sA = stLA + pp * PS + rr * RS + q * 4;
                const float* sB = stH  + pp * PS + rr * RS + q * 4;
                const float4 vA = make_float4(sA[0], sA[1], sA[2], sA[3]);
                const float4 vB = make_float4(sB[0], sB[1], sB[2], sB[3]);
                *(float4*)&elaW [(size_t)gg * 128 + cb + q * 4] = vA;
                *(float4*)&eentW[(size_t)gg * 128 + cb + q * 4] = vB;
            }
            __syncwarp();
        }
        if (l == 0) {
            out[O_LOG_ALPHA + b] = laf;
            out[O_ENT + b]       = hf;
        }
    }
}

extern "C" void kernel_launch(void* const* d_in, const int* in_sizes, int n_in,
                              void* d_out, int out_size)
{
    const float* fwd_ts  = (const float*)d_in[0];
    const float* fwd_ms  = (const float*)d_in[1];
    const float* bwd_ts  = (const float*)d_in[2];
    const int*   lengths = (const int*)d_in[4];
    float* out = (float*)d_out;

    cudaMemcpyAsync(out + O_FWD_TS, fwd_ts, sizeof(float) * 131072,
                    cudaMemcpyDeviceToDevice);
    cudaMemcpyAsync(out + O_FWD_MS, fwd_ms, sizeof(float) * 131072,
                    cudaMemcpyDeviceToDevice);

    dim3 grid(64, 9);
    tok_kernel<<<grid, 64>>>(fwd_ts, bwd_ts, lengths, out);
}

// round 9
// speedup vs baseline: 4.0348x; 1.1666x over previous
#include <cuda_runtime.h>

#define NEGV -1000000000.0f

// Output layout (float offsets), reference return order:
// fwd_ts, fwd_ms, log_alpha, edge_log_alpha, log_betas, elb, ent, edge_ent
constexpr size_t O_FWD_TS    = 0;
constexpr size_t O_FWD_MS    = 131072;
constexpr size_t O_LOG_ALPHA = 262144;
constexpr size_t O_EDGE_LA   = 262208;
constexpr size_t O_LOG_BETAS = 393280;
constexpr size_t O_ELB       = 401472;
constexpr size_t O_ENT       = 17178688;
constexpr size_t O_EDGE_ENT  = 17178752;

// Staging strides (floats): PS%32==1, RS%8==2 -> compute-side STS conflict-free.
constexpr int RS    = 34;
constexpr int PS    = 16 * RS + 1;   // 545
constexpr int STAGE = 8 * PS;        // 4360 floats / warp

// cross-lane (4-lane group) LSE reduce of 4 local terms -> (max, sum) pair
__device__ __forceinline__ void lse_reduce4(float a0, float a1, float a2, float a3,
                                            float& M, float& S) {
    float mx = fmaxf(fmaxf(a0, a1), fmaxf(a2, a3));
    float s = (__expf(a0 - mx) + __expf(a1 - mx)) +
              (__expf(a2 - mx) + __expf(a3 - mx));
    float Mt = fmaxf(mx, __shfl_xor_sync(0xffffffffu, mx, 1));
    Mt = fmaxf(Mt, __shfl_xor_sync(0xffffffffu, Mt, 2));
    float sg = s * __expf(mx - Mt);
    sg += __shfl_xor_sync(0xffffffffu, sg, 1);
    sg += __shfl_xor_sync(0xffffffffu, sg, 2);
    M = Mt; S = sg;
}

// 64-thread blocks (2 warps), 4 lanes/problem, 4 rows/lane.
//  blockIdx.y < 8 : backward, deep-pipelined (chain = scalar combine only).
//  blockIdx.y == 8: forward+entropy (R4 + parallel-u trim).
__global__ void __launch_bounds__(64)
tok_kernel(const float* __restrict__ fwd_ts,
           const float* __restrict__ bwd_ts,
           const int*   __restrict__ lengths,
           float* __restrict__ out)
{
    __shared__ float sh[2048 + 2 * STAGE];   // 43072 B

    const int tid  = threadIdx.x;
    const int lane = tid & 31;
    const int w    = tid >> 5;
    const int l    = lane & 3;      // lane within 4-lane group
    const int p    = lane >> 2;     // problem within warp (0..7)
    const int rk0  = l * 4;         // first row of this lane
    const int q    = lane & 7;      // flush: float4 slot
    const int rsub = lane >> 3;     // flush: row sub-index

    if (blockIdx.y < 8) {
        // =================== backward scans (deep pipeline) ===================
        const int b   = blockIdx.x;
        const int len = lengths[b];
        const int j0w = (int)blockIdx.y * 16 + w * 8;
        const int j   = j0w + p;
        const int i0  = 127 - j;

        const float* g = bwd_ts + (size_t)b * 2048;
        for (int x = tid; x < 2048; x += 64)
            sh[(x & 127) * 16 + (x >> 7)] = g[x];
        __syncthreads();

        float* stageW = sh + 2048 + w * STAGE;
        float* stp    = stageW + p * PS + rk0 * RS;
        float* elbW   = out + O_ELB + (size_t)(b * 128 + j0w) * 2048;
        const int cb0 = (120 - j0w) & ~31;     // multiple of 32, <= min i0

        // ---- pipeline state ----
        // la = la(c-1); w0..w3 = la(c-1-rk0 .. c-4-rk0)
        // (Rm,Rs) = rows 1..15 of column c; (Qm,Qs) = rows 2..15 of column c+1
        // cur = emission cands for column c; nxt = for column c+1
        float la = 0.f, lb = 0.f;
        float w0 = 0.f, w1 = 0.f, w2 = 0.f, w3 = 0.f;
        float Rm, Rs, Qm, Qs;
        float cur0, cur1, cur2, cur3, nxt0, nxt1, nxt2, nxt3;
        float4 t4c, t4m;
        {   // prologue at cb0: all prior la's are exactly 0
            t4c = *(const float4*)&sh[cb0 * 16 + rk0];
            t4m = *(const float4*)&sh[min(cb0 + 1, 127) * 16 + rk0];
            const int k0 = min(j, cb0 - i0);
            cur0 = (rk0     <= k0) ? t4c.x : NEGV;
            cur1 = (rk0 + 1 <= k0) ? t4c.y : NEGV;
            cur2 = (rk0 + 2 <= k0) ? t4c.z : NEGV;
            cur3 = (rk0 + 3 <= k0) ? t4c.w : NEGV;
            const int k1 = min(j, cb0 + 1 - i0);
            nxt0 = (rk0     <= k1) ? t4m.x : NEGV;
            nxt1 = (rk0 + 1 <= k1) ? t4m.y : NEGV;
            nxt2 = (rk0 + 2 <= k1) ? t4m.z : NEGV;
            nxt3 = (rk0 + 3 <= k1) ? t4m.w : NEGV;
            // R: rows 1..15 of col cb0 (exclude lane0 slot0 = row0)
            lse_reduce4((l > 0) ? cur0 : NEGV, cur1, cur2, cur3, Rm, Rs);
            // Q: rows 2..15 of col cb0+1 (exclude lane0 slots 0,1)
            lse_reduce4((l > 0) ? nxt0 : NEGV, (l > 0) ? nxt1 : NEGV,
                        nxt2, nxt3, Qm, Qs);
        }

        for (int cb = 0; cb < 128; cb += 32) {
            if (cb < cb0) {   // all-trivial prefix: bulk NEG fill
                const float4 n4 = make_float4(NEGV, NEGV, NEGV, NEGV);
#pragma unroll 8
                for (int t = 0; t < 32; ++t) {
                    const int gg = t * 4 + rsub;
                    *(float4*)&elbW[(size_t)gg * 128 + cb + q * 4] = n4;
                }
                continue;
            }
#pragma unroll 2
            for (int cc = 0; cc < 32; ++cc) {
                const int c = cb + cc;
                if (c < len) {   // uniform branch
                    // -- off-chain: vector cands for col c+2 (rows 2..15 + lane0 r2,r3)
                    const int cx = c + 2;
                    const float4 X = *(const float4*)&sh[min(cx, 127) * 16 + rk0];
                    const float s2v = __shfl_up_sync(0xffffffffu, w2, 1);
                    const float s3v = __shfl_up_sync(0xffffffffu, w3, 1);
                    const int kx = min(j, cx - i0);
                    const float p0 = (l > 0 && rk0     <= kx) ? X.x + s2v : NEGV;
                    const float p1 = (l > 0 && rk0 + 1 <= kx) ? X.y + s3v : NEGV;
                    const float p2 = (rk0 + 2 <= kx) ? X.z + w0 : NEGV;
                    const float p3 = (rk0 + 3 <= kx) ? X.w + w1 : NEGV;
                    float QmN, QsN;
                    lse_reduce4(p0, p1, p2, p3, QmN, QsN);
                    // -- off-chain: fold row1 of col c+1 into Q -> R_{c+1}
                    const float y1 = (1 <= min(j, c + 1 - i0)) ? t4m.y + la : NEGV;
                    const float RmN = fmaxf(Qm, y1);
                    const float RsN = Qs * __expf(Qm - RmN) + __expf(y1 - RmN);
                    // -- ON-CHAIN combine for column c (scalar, lane0 real)
                    const float c0 = ((c >= i0) ? t4c.x : 0.f) + la;
                    const float mx = fmaxf(Rm, c0);
                    const float s  = Rs * __expf(Rm - mx) + __expf(c0 - mx);
                    const float laN = mx + __logf(s);
                    lb = (c == len - 1) ? laN : lb;
                    // -- emission for column c
                    stp[cc]          = (l == 0) ? ((c >= i0) ? c0 : NEGV) : cur0;
                    stp[RS + cc]     = cur1;
                    stp[2 * RS + cc] = cur2;
                    stp[3 * RS + cc] = cur3;
                    // -- rotate pipeline
                    cur0 = nxt0; cur1 = (l == 0) ? y1 : nxt1;
                    cur2 = nxt2; cur3 = nxt3;
                    nxt0 = p0; nxt1 = p1; nxt2 = p2; nxt3 = p3;
                    w3 = w2; w2 = w1; w1 = w0;
                    w0 = (l == 0) ? laN : s3v;
                    la = laN;
                    Rm = RmN; Rs = RsN; Qm = QmN; Qs = QsN;
                    t4c = t4m; t4m = X;
                } else {
                    // tail: cand = t + NEG where emask, else NEG (no state needed)
                    const float4 T = *(const float4*)&sh[c * 16 + rk0];
                    const int kc = min(j, c - i0);
                    stp[cc]          = (rk0     <= kc) ? T.x + NEGV : NEGV;
                    stp[RS + cc]     = (rk0 + 1 <= kc) ? T.y + NEGV : NEGV;
                    stp[2 * RS + cc] = (rk0 + 2 <= kc) ? T.z + NEGV : NEGV;
                    stp[3 * RS + cc] = (rk0 + 3 <= kc) ? T.w + NEGV : NEGV;
                }
            }
            __syncwarp();
#pragma unroll 4
            for (int t = 0; t < 32; ++t) {
                const int gg = t * 4 + rsub;
                const int pp = gg >> 4, rr = gg & 15;
                const float* s2 = stageW + pp * PS + rr * RS + q * 4;
                const float4 v = make_float4(s2[0], s2[1], s2[2], s2[3]);
                *(float4*)&elbW[(size_t)gg * 128 + cb + q * 4] = v;
            }
            __syncwarp();
        }
        if (l == 0)
            out[O_LOG_BETAS + (size_t)b * 128 + j] = lb;

    } else {
        // ========== forward + entropy (R4 + parallel-u trim) ==========
        if (blockIdx.x >= 8 || w != 0) return;
        const int b   = (int)blockIdx.x * 8 + p;
        const int len = lengths[b];

        const float* tr = fwd_ts + (size_t)b * 2048 + (size_t)rk0 * 128;
        float* stLA = sh;
        float* stH  = sh + STAGE;
        float* elaW  = out + O_EDGE_LA  + (size_t)blockIdx.x * 8 * 2048;
        float* eentW = out + O_EDGE_ENT + (size_t)blockIdx.x * 8 * 2048;

        float w0 = 0.f, w1 = 0.f, w2 = 0.f, w3 = 0.f;
        float h0 = 0.f, h1 = 0.f, h2 = 0.f, h3 = 0.f;
        float laf = 0.f, hf = 0.f;
        float t0 = tr[0], t1 = tr[128], t2 = tr[256], t3 = tr[384];
        float* st = stLA + p * PS + rk0 * RS;
        float* sh2 = stH + p * PS + rk0 * RS;

        for (int cb = 0; cb < 128; cb += 32) {
#pragma unroll 2
            for (int cc = 0; cc < 32; ++cc) {
                const int jj = cb + cc;
                float n0 = 0.f, n1 = 0.f, n2 = 0.f, n3 = 0.f;
                if (jj < 127) {   // prefetch next column (off-chain)
                    n0 = tr[jj + 1];       n1 = tr[128 + jj + 1];
                    n2 = tr[256 + jj + 1]; n3 = tr[384 + jj + 1];
                }
                const bool in = (jj < len);
                const bool m0 = in && (rk0     <= jj);
                const bool m1 = in && (rk0 + 1 <= jj);
                const bool m2 = in && (rk0 + 2 <= jj);
                const bool m3 = in && (rk0 + 3 <= jj);
                const float c0 = t0 + (m0 ? w0 : NEGV);
                const float c1 = t1 + (m1 ? w1 : NEGV);
                const float c2 = t2 + (m2 ? w2 : NEGV);
                const float c3 = t3 + (m3 ? w3 : NEGV);
                float mx = fmaxf(fmaxf(c0, c1), fmaxf(c2, c3));
                mx = fmaxf(mx, __shfl_xor_sync(0xffffffffu, mx, 1));
                mx = fmaxf(mx, __shfl_xor_sync(0xffffffffu, mx, 2));
                const float e0 = __expf(c0 - mx), e1 = __expf(c1 - mx);
                const float e2 = __expf(c2 - mx), e3 = __expf(c3 - mx);
                // parallel reductions: sum of e and sum of e*(h-c)
                float ssr = (e0 + e1) + (e2 + e3);
                float ulr = (e0 * (h0 - c0) + e1 * (h1 - c1)) +
                            (e2 * (h2 - c2) + e3 * (h3 - c3));
                ssr += __shfl_xor_sync(0xffffffffu, ssr, 1);
                ulr += __shfl_xor_sync(0xffffffffu, ulr, 1);
                ssr += __shfl_xor_sync(0xffffffffu, ssr, 2);
                ulr += __shfl_xor_sync(0xffffffffu, ulr, 2);
                const float la  = mx + __logf(ssr);
                const float inv = __frcp_rn(ssr);
                const float hh  = in ? (la + ulr * inv) : 0.f;
                // per-edge outputs: R4 formulas, unchanged
                const float g0 = m0 ? (e0 * inv) * ((h0 + la) - c0) : 0.f;
                const float g1 = m1 ? (e1 * inv) * ((h1 + la) - c1) : 0.f;
                const float g2 = m2 ? (e2 * inv) * ((h2 + la) - c2) : 0.f;
                const float g3 = m3 ? (e3 * inv) * ((h3 + la) - c3) : 0.f;

                laf = (jj == len - 1) ? la : laf;
                hf  = (jj == len - 1) ? hh : hf;

                st[cc] = c0;  st[RS + cc] = c1;  st[2 * RS + cc] = c2;  st[3 * RS + cc] = c3;
                sh2[cc] = g0; sh2[RS + cc] = g1; sh2[2 * RS + cc] = g2; sh2[3 * RS + cc] = g3;

                const float upw = __shfl_up_sync(0xffffffffu, w3, 1);
                const float uph = __shfl_up_sync(0xffffffffu, h3, 1);
                w3 = w2; w2 = w1; w1 = w0; w0 = (l == 0) ? la : upw;
                h3 = h2; h2 = h1; h1 = h0; h0 = (l == 0) ? hh : uph;
                t0 = n0; t1 = n1; t2 = n2; t3 = n3;
            }
            __syncwarp();
#pragma unroll 4
            for (int t = 0; t < 32; ++t) {
                const int gg = t * 4 + rsub;
                const int pp = gg >> 4, rr = gg & 15;
                const float* sA = stLA + pp * PS + rr * RS + q * 4;
                const float* sB = stH  + pp * PS + rr * RS + q * 4;
                const float4 vA = make_float4(sA[0], sA[1], sA[2], sA[3]);
                const float4 vB = make_float4(sB[0], sB[1], sB[2], sB[3]);
                *(float4*)&elaW [(size_t)gg * 128 + cb + q * 4] = vA;
                *(float4*)&eentW[(size_t)gg * 128 + cb + q * 4] = vB;
            }
            __syncwarp();
        }
        if (l == 0) {
            out[O_LOG_ALPHA + b] = laf;
            out[O_ENT + b]       = hf;
        }
    }
}

extern "C" void kernel_launch(void* const* d_in, const int* in_sizes, int n_in,
                              void* d_out, int out_size)
{
    const float* fwd_ts  = (const float*)d_in[0];
    const float* fwd_ms  = (const float*)d_in[1];
    const float* bwd_ts  = (const float*)d_in[2];
    const int*   lengths = (const int*)d_in[4];
    float* out = (float*)d_out;

    cudaMemcpyAsync(out + O_FWD_TS, fwd_ts, sizeof(float) * 131072,
                    cudaMemcpyDeviceToDevice);
    cudaMemcpyAsync(out + O_FWD_MS, fwd_ms, sizeof(float) * 131072,
                    cudaMemcpyDeviceToDevice);

    dim3 grid(64, 9);
    tok_kernel<<<grid, 64>>>(fwd_ts, bwd_ts, lengths, out);
}